// round 6
// baseline (speedup 1.0000x reference)
#include <cuda_runtime.h>
#include <math_constants.h>

#define N_NODES 100000
#define N_EDGES 1600000
#define D1 32
#define D2 16
#define CAP 64            // bucket capacity per dst; P(deg>=64) ~ 1e-19

// ---------------- scratch (device globals; no allocation allowed) -------------
__device__ __align__(16) float g_q   [N_NODES * D1];
__device__ __align__(16) float g_k   [N_NODES * D1];
__device__ __align__(16) float g_v   [N_NODES * D1];
__device__ __align__(16) float g_skip[N_NODES * D1];
__device__ __align__(16) float g_h   [N_NODES * D1];
__device__ int   g_deg   [N_NODES];
__device__ int   g_bucket[(size_t)N_NODES * CAP];

// ---------------- layer-1 projection (also zeroes deg) -----------------------
__global__ __launch_bounds__(256) void proj1_kernel(
        const float* __restrict__ x,
        const float* __restrict__ Wq, const float* __restrict__ bq,
        const float* __restrict__ Wk, const float* __restrict__ bk,
        const float* __restrict__ Wv, const float* __restrict__ bv,
        const float* __restrict__ Ws, const float* __restrict__ bs,
        int n) {
    constexpr int NPB = 256 / D1;              // 8 nodes per block
    __shared__ float sW[4][D1 * D1];
    __shared__ float sx[NPB][D1];
    int t = threadIdx.x;
    for (int i = t; i < D1 * D1; i += 256) {
        sW[0][i] = Wq[i]; sW[1][i] = Wk[i]; sW[2][i] = Wv[i]; sW[3][i] = Ws[i];
    }
    int node0 = blockIdx.x * NPB;
    for (int i = t; i < NPB * D1; i += 256) {
        int nn = node0 + (i >> 5);
        sx[i >> 5][i & 31] = (nn < n) ? x[(size_t)nn * D1 + (i & 31)] : 0.0f;
    }
    __syncthreads();
    int ln = t >> 5;
    int j  = t & 31;
    int node = node0 + ln;
    if (node >= n) return;
    float aq = bq[j], ak = bk[j], av = bv[j], as_ = bs[j];
    #pragma unroll
    for (int i = 0; i < D1; i++) {
        float xi = sx[ln][i];
        aq  = fmaf(xi, sW[0][i * D1 + j], aq);
        ak  = fmaf(xi, sW[1][i * D1 + j], ak);
        av  = fmaf(xi, sW[2][i * D1 + j], av);
        as_ = fmaf(xi, sW[3][i * D1 + j], as_);
    }
    int o = node * D1 + j;
    g_q[o] = aq; g_k[o] = ak; g_v[o] = av; g_skip[o] = as_;
    if (j == 0) g_deg[node] = 0;               // init for scatter
}

// ---------------- bucket build: group edges by dst ----------------------------
__global__ __launch_bounds__(256) void scatter_kernel(
        const int* __restrict__ src, const int* __restrict__ dst, int nE) {
    int e = blockIdx.x * blockDim.x + threadIdx.x;
    if (e >= nE) return;
    int d = dst[e];
    int pos = atomicAdd(g_deg + d, 1);
    if (pos < CAP) g_bucket[(size_t)d * CAP + pos] = src[e];
}

// ---------------- layer-1 attention: warp per dst, lane = dim -----------------
// acc/sum in registers; epilogue writes h = relu(acc/(sum+eps) + skip).
__global__ __launch_bounds__(256) void edgeL1_kernel(float scale, int n) {
    int warp = (blockIdx.x * blockDim.x + threadIdx.x) >> 5;
    int lane = threadIdx.x & 31;
    if (warp >= n) return;
    int d = warp;
    int deg = min(g_deg[d], CAP);
    float qj  = g_q[(size_t)d * D1 + lane];
    int sv0 = g_bucket[(size_t)d * CAP + lane];        // slots 0..31
    int sv1 = g_bucket[(size_t)d * CAP + 32 + lane];   // slots 32..63
    float acc = 0.0f, sum = 0.0f;
    #pragma unroll 2
    for (int t = 0; t < deg; t++) {
        int s = (t < 32) ? __shfl_sync(0xffffffffu, sv0, t)
                         : __shfl_sync(0xffffffffu, sv1, t - 32);
        float kv = g_k[(size_t)s * D1 + lane];         // coalesced 128B row
        float p = qj * kv;
        p += __shfl_xor_sync(0xffffffffu, p, 16);
        p += __shfl_xor_sync(0xffffffffu, p, 8);
        p += __shfl_xor_sync(0xffffffffu, p, 4);
        p += __shfl_xor_sync(0xffffffffu, p, 2);
        p += __shfl_xor_sync(0xffffffffu, p, 1);
        float w = __expf(fminf(p * scale, 75.0f));
        float vv = g_v[(size_t)s * D1 + lane];         // coalesced 128B row
        acc = fmaf(vv, w, acc);
        sum += w;
    }
    float h = acc / (sum + 1e-16f) + g_skip[(size_t)d * D1 + lane];
    g_h[(size_t)d * D1 + lane] = fmaxf(h, 0.0f);
}

// ---------------- layer-2 projection (32 -> 16), reads g_h --------------------
__global__ __launch_bounds__(256) void proj2_kernel(
        const float* __restrict__ Wq, const float* __restrict__ bq,
        const float* __restrict__ Wk, const float* __restrict__ bk,
        const float* __restrict__ Wv, const float* __restrict__ bv,
        const float* __restrict__ Ws, const float* __restrict__ bs,
        int n) {
    constexpr int NPB = 256 / D2;              // 16 nodes per block
    __shared__ float sW[4][D1 * D2];
    __shared__ float sh[NPB][D1];
    int t = threadIdx.x;
    for (int i = t; i < D1 * D2; i += 256) {
        sW[0][i] = Wq[i]; sW[1][i] = Wk[i]; sW[2][i] = Wv[i]; sW[3][i] = Ws[i];
    }
    int node0 = blockIdx.x * NPB;
    #pragma unroll
    for (int r = 0; r < 2; r++) {
        int i = t + r * 256;                   // 0..511 = 16 nodes * 32 dims
        int nn = node0 + (i >> 5);
        sh[i >> 5][i & 31] = (nn < n) ? g_h[(size_t)nn * D1 + (i & 31)] : 0.0f;
    }
    __syncthreads();
    int ln = t >> 4;
    int j  = t & 15;
    int node = node0 + ln;
    if (node >= n) return;
    float aq = bq[j], ak = bk[j], av = bv[j], as_ = bs[j];
    #pragma unroll
    for (int i = 0; i < D1; i++) {
        float xi = sh[ln][i];
        aq  = fmaf(xi, sW[0][i * D2 + j], aq);
        ak  = fmaf(xi, sW[1][i * D2 + j], ak);
        av  = fmaf(xi, sW[2][i * D2 + j], av);
        as_ = fmaf(xi, sW[3][i * D2 + j], as_);
    }
    int o = node * D2 + j;
    g_q[o] = aq; g_k[o] = ak; g_v[o] = av; g_skip[o] = as_;
}

// ---------------- layer-2 attention + output linear, fused --------------------
// warp handles 2 dsts (lanes 0-15 / 16-31), width-16 shfls throughout.
__global__ __launch_bounds__(256) void edgeL2_out_kernel(
        const float* __restrict__ Wo, const float* __restrict__ bo,
        float* __restrict__ out, float scale, int n) {
    int warp = (blockIdx.x * blockDim.x + threadIdx.x) >> 5;
    int lane = threadIdx.x & 31;
    int j = lane & 15, half = lane >> 4;
    int d = warp * 2 + half;
    bool vd = (d < n);
    int dd = vd ? d : 0;
    int deg = vd ? min(g_deg[dd], CAP) : 0;
    float qj = g_q[(size_t)dd * D2 + j];
    int degmax = max(deg, __shfl_xor_sync(0xffffffffu, deg, 16));
    float acc = 0.0f, sum = 0.0f;
    for (int base = 0; base < degmax; base += 16) {
        int sv = g_bucket[(size_t)dd * CAP + base + j];     // 16 slots per half
        int chunk = min(16, degmax - base);
        for (int t = 0; t < chunk; t++) {
            int s = __shfl_sync(0xffffffffu, sv, t, 16);
            bool ev = (base + t) < deg;
            float kv = g_k[(size_t)s * D2 + j];
            float p = qj * kv;
            p += __shfl_xor_sync(0xffffffffu, p, 8, 16);
            p += __shfl_xor_sync(0xffffffffu, p, 4, 16);
            p += __shfl_xor_sync(0xffffffffu, p, 2, 16);
            p += __shfl_xor_sync(0xffffffffu, p, 1, 16);
            float w = ev ? __expf(fminf(p * scale, 75.0f)) : 0.0f;
            float vv = g_v[(size_t)s * D2 + j];
            acc = fmaf(vv, w, acc);
            sum += w;
        }
    }
    float val = acc / (sum + 1e-16f) + g_skip[(size_t)dd * D2 + j];
    val = fmaxf(val, 0.0f);
    float p0 = val * Wo[j * 2 + 0];
    float p1 = val * Wo[j * 2 + 1];
    #pragma unroll
    for (int o = 8; o; o >>= 1) {
        p0 += __shfl_xor_sync(0xffffffffu, p0, o, 16);
        p1 += __shfl_xor_sync(0xffffffffu, p1, o, 16);
    }
    if (j == 0 && vd) {
        out[d * 2 + 0] = p0 + bo[0];
        out[d * 2 + 1] = p1 + bo[1];
    }
}

// ---------------- launch ------------------------------------------------------
extern "C" void kernel_launch(void* const* d_in, const int* in_sizes, int n_in,
                              void* d_out, int out_size) {
    const int*   ei  = (const int*)d_in[0];
    const float* emb = (const float*)d_in[1];
    const float *Wq1 = (const float*)d_in[2],  *bq1 = (const float*)d_in[3];
    const float *Wk1 = (const float*)d_in[4],  *bk1 = (const float*)d_in[5];
    const float *Wv1 = (const float*)d_in[6],  *bv1 = (const float*)d_in[7];
    const float *Ws1 = (const float*)d_in[8],  *bs1 = (const float*)d_in[9];
    const float *Wq2 = (const float*)d_in[10], *bq2 = (const float*)d_in[11];
    const float *Wk2 = (const float*)d_in[12], *bk2 = (const float*)d_in[13];
    const float *Wv2 = (const float*)d_in[14], *bv2 = (const float*)d_in[15];
    const float *Ws2 = (const float*)d_in[16], *bs2 = (const float*)d_in[17];
    const float *Wo  = (const float*)d_in[18], *bo  = (const float*)d_in[19];
    float* out = (float*)d_out;

    int E = in_sizes[0] / 2;
    int N = in_sizes[1] / D1;
    const int* src = ei;
    const int* dst = ei + E;

    const int TB = 256;
    int gP1 = (N + 7) / 8;                     // 8 nodes / block
    int gSC = (E + TB - 1) / TB;
    int gE1 = (N + 7) / 8;                     // 8 warps = 8 dsts / block
    int gP2 = (N + 15) / 16;
    int gE2 = (N + 15) / 16;                   // 8 warps = 16 dsts / block

    float s1 = 1.0f / sqrtf((float)D1);
    float s2 = 1.0f / sqrtf((float)D2);

    proj1_kernel<<<gP1, TB>>>(emb, Wq1, bq1, Wk1, bk1, Wv1, bv1, Ws1, bs1, N);
    scatter_kernel<<<gSC, TB>>>(src, dst, E);
    edgeL1_kernel<<<gE1, TB>>>(s1, N);
    proj2_kernel<<<gP2, TB>>>(Wq2, bq2, Wk2, bk2, Wv2, bv2, Ws2, bs2, N);
    edgeL2_out_kernel<<<gE2, TB>>>(Wo, bo, out, s2, N);
}

// round 7
// speedup vs baseline: 1.4775x; 1.4775x over previous
#include <cuda_runtime.h>
#include <math_constants.h>

#define N_NODES 100000
#define N_EDGES 1600000
#define D1 32
#define D2 16
#define CAP 64            // bucket capacity per dst; P(deg>=64) ~ 1e-13 total

// ---------------- scratch (device globals; no allocation allowed) -------------
__device__ __align__(16) float g_q   [N_NODES * D1];
__device__ __align__(16) float g_k   [N_NODES * D1];
__device__ __align__(16) float g_v   [N_NODES * D1];
__device__ __align__(16) float g_skip[N_NODES * D1];
__device__ __align__(16) float g_q2  [N_NODES * D2];
__device__ __align__(16) float g_k2  [N_NODES * D2];
__device__ __align__(16) float g_v2  [N_NODES * D2];
__device__ __align__(16) float g_sk2 [N_NODES * D2];
__device__ int   g_deg   [N_NODES];
__device__ int   g_bucket[(size_t)N_NODES * CAP];

#define FULL 0xffffffffu

// ---------------- layer-1 projection (also zeroes deg) -----------------------
__global__ __launch_bounds__(256) void proj1_kernel(
        const float* __restrict__ x,
        const float* __restrict__ Wq, const float* __restrict__ bq,
        const float* __restrict__ Wk, const float* __restrict__ bk,
        const float* __restrict__ Wv, const float* __restrict__ bv,
        const float* __restrict__ Ws, const float* __restrict__ bs,
        int n) {
    constexpr int NPB = 256 / D1;              // 8 nodes per block
    __shared__ float sW[4][D1 * D1];
    __shared__ float sx[NPB][D1];
    int t = threadIdx.x;
    for (int i = t; i < D1 * D1; i += 256) {
        sW[0][i] = Wq[i]; sW[1][i] = Wk[i]; sW[2][i] = Wv[i]; sW[3][i] = Ws[i];
    }
    int node0 = blockIdx.x * NPB;
    for (int i = t; i < NPB * D1; i += 256) {
        int nn = node0 + (i >> 5);
        sx[i >> 5][i & 31] = (nn < n) ? x[(size_t)nn * D1 + (i & 31)] : 0.0f;
    }
    __syncthreads();
    int ln = t >> 5;
    int j  = t & 31;
    int node = node0 + ln;
    if (node >= n) return;
    float aq = bq[j], ak = bk[j], av = bv[j], as_ = bs[j];
    #pragma unroll
    for (int i = 0; i < D1; i++) {
        float xi = sx[ln][i];
        aq  = fmaf(xi, sW[0][i * D1 + j], aq);
        ak  = fmaf(xi, sW[1][i * D1 + j], ak);
        av  = fmaf(xi, sW[2][i * D1 + j], av);
        as_ = fmaf(xi, sW[3][i * D1 + j], as_);
    }
    int o = node * D1 + j;
    g_q[o] = aq; g_k[o] = ak; g_v[o] = av; g_skip[o] = as_;
    if (j == 0) g_deg[node] = 0;
}

// ---------------- bucket build: group edges by dst ----------------------------
__global__ __launch_bounds__(256) void scatter_kernel(
        const int* __restrict__ src, const int* __restrict__ dst, int nE) {
    int e = blockIdx.x * blockDim.x + threadIdx.x;
    if (e >= nE) return;
    int d = dst[e];
    int pos = atomicAdd(g_deg + d, 1);
    if (pos < CAP) g_bucket[(size_t)d * CAP + pos] = src[e];
}

// ---------------- layer-1 attention + layer-2 projection, fused ---------------
// warp = one dst; 8 parallel edge slots x 4 lanes. lane covers dims
// {sub*4..+3} U {16+sub*4..+3} (two float4). No atomics; h stays in SMEM and
// phase B projects it to layer-2 q/k/v/skip.
__global__ __launch_bounds__(256) void edgeL1_proj2_kernel(
        const float* __restrict__ Wq, const float* __restrict__ bq,
        const float* __restrict__ Wk, const float* __restrict__ bk,
        const float* __restrict__ Wv, const float* __restrict__ bv,
        const float* __restrict__ Ws, const float* __restrict__ bs,
        float scale, int n) {
    __shared__ float sW[4][D1 * D2];
    __shared__ float sb[4][D2];
    __shared__ float sh[8][D1];
    int t = threadIdx.x;
    for (int i = t; i < D1 * D2; i += 256) {
        sW[0][i] = Wq[i]; sW[1][i] = Wk[i]; sW[2][i] = Wv[i]; sW[3][i] = Ws[i];
    }
    if (t < 4 * D2) sb[t >> 4][t & 15] = (t < D2) ? bq[t]
                       : (t < 2 * D2) ? bk[t - D2]
                       : (t < 3 * D2) ? bv[t - 2 * D2] : bs[t - 3 * D2];
    __syncthreads();

    int warp = t >> 5;
    int lane = t & 31;
    int slot = lane >> 2;            // 0..7
    int sub  = lane & 3;             // 0..3
    int d = blockIdx.x * 8 + warp;
    bool vd = (d < n);
    int dd = vd ? d : 0;

    int deg = vd ? min(g_deg[dd], CAP) : 0;
    const float4* q4 = (const float4*)(g_q + (size_t)dd * D1);
    float4 qa = q4[sub], qb = q4[4 + sub];
    int sv0 = g_bucket[(size_t)dd * CAP + lane];
    int sv1 = g_bucket[(size_t)dd * CAP + 32 + lane];

    float4 aa = {0,0,0,0}, ab = {0,0,0,0};
    float sum = 0.0f;
    int iters = (deg + 7) >> 3;
    for (int it = 0; it < iters; it++) {
        int e = slot + it * 8;
        int i0 = __shfl_sync(FULL, sv0, e & 31);
        int i1 = __shfl_sync(FULL, sv1, e & 31);
        bool act = (e < deg);
        int s = act ? ((e < 32) ? i0 : i1) : 0;
        const float4* k4 = (const float4*)(g_k + (size_t)s * D1);
        float4 ka = k4[sub], kb = k4[4 + sub];
        float p = qa.x*ka.x + qa.y*ka.y + qa.z*ka.z + qa.w*ka.w
                + qb.x*kb.x + qb.y*kb.y + qb.z*kb.z + qb.w*kb.w;
        p += __shfl_xor_sync(FULL, p, 1, 4);
        p += __shfl_xor_sync(FULL, p, 2, 4);
        float w = act ? __expf(fminf(p * scale, 75.0f)) : 0.0f;
        const float4* v4 = (const float4*)(g_v + (size_t)s * D1);
        float4 va = v4[sub], vb = v4[4 + sub];
        aa.x = fmaf(va.x, w, aa.x); aa.y = fmaf(va.y, w, aa.y);
        aa.z = fmaf(va.z, w, aa.z); aa.w = fmaf(va.w, w, aa.w);
        ab.x = fmaf(vb.x, w, ab.x); ab.y = fmaf(vb.y, w, ab.y);
        ab.z = fmaf(vb.z, w, ab.z); ab.w = fmaf(vb.w, w, ab.w);
        sum += w;
    }
    // reduce across the 8 slots (lane bits 2..4)
    #pragma unroll
    for (int o = 4; o < 32; o <<= 1) {
        aa.x += __shfl_xor_sync(FULL, aa.x, o); aa.y += __shfl_xor_sync(FULL, aa.y, o);
        aa.z += __shfl_xor_sync(FULL, aa.z, o); aa.w += __shfl_xor_sync(FULL, aa.w, o);
        ab.x += __shfl_xor_sync(FULL, ab.x, o); ab.y += __shfl_xor_sync(FULL, ab.y, o);
        ab.z += __shfl_xor_sync(FULL, ab.z, o); ab.w += __shfl_xor_sync(FULL, ab.w, o);
        sum  += __shfl_xor_sync(FULL, sum,  o);
    }
    if (vd && slot == 0) {
        const float4* sk4 = (const float4*)(g_skip + (size_t)dd * D1);
        float4 sk_a = sk4[sub], sk_b = sk4[4 + sub];
        float inv = 1.0f / (sum + 1e-16f);
        sh[warp][sub*4+0]    = fmaxf(aa.x*inv + sk_a.x, 0.0f);
        sh[warp][sub*4+1]    = fmaxf(aa.y*inv + sk_a.y, 0.0f);
        sh[warp][sub*4+2]    = fmaxf(aa.z*inv + sk_a.z, 0.0f);
        sh[warp][sub*4+3]    = fmaxf(aa.w*inv + sk_a.w, 0.0f);
        sh[warp][16+sub*4+0] = fmaxf(ab.x*inv + sk_b.x, 0.0f);
        sh[warp][16+sub*4+1] = fmaxf(ab.y*inv + sk_b.y, 0.0f);
        sh[warp][16+sub*4+2] = fmaxf(ab.z*inv + sk_b.z, 0.0f);
        sh[warp][16+sub*4+3] = fmaxf(ab.w*inv + sk_b.w, 0.0f);
    }
    __syncthreads();
    // phase B: layer-2 projection 32->16. thread = (node ln, m in {0,1}, j);
    // handles matrices m and m+2.
    int ln = t >> 5;
    int m  = (t >> 4) & 1;
    int j  = t & 15;
    int node = blockIdx.x * 8 + ln;
    if (node >= n) return;
    float a0 = sb[m][j], a1 = sb[m + 2][j];
    #pragma unroll
    for (int i = 0; i < D1; i++) {
        float hi = sh[ln][i];
        a0 = fmaf(hi, sW[m][i * D2 + j], a0);
        a1 = fmaf(hi, sW[m + 2][i * D2 + j], a1);
    }
    int o = node * D2 + j;
    if (m == 0) { g_q2[o] = a0; g_v2[o] = a1; }
    else        { g_k2[o] = a0; g_sk2[o] = a1; }
}

// ---------------- layer-2 attention + output linear, fused --------------------
// warp = one dst; 8 slots x 4 lanes; lane covers dims sub*4..+3 (one float4).
__global__ __launch_bounds__(256) void edgeL2_out_kernel(
        const float* __restrict__ Wo, const float* __restrict__ bo,
        float* __restrict__ out, float scale, int n) {
    int t = threadIdx.x;
    int warp = t >> 5;
    int lane = t & 31;
    int slot = lane >> 2;
    int sub  = lane & 3;
    int d = blockIdx.x * 8 + warp;
    if (d >= n) return;

    int deg = min(g_deg[d], CAP);
    float4 qv = ((const float4*)(g_q2 + (size_t)d * D2))[sub];
    int sv0 = g_bucket[(size_t)d * CAP + lane];
    int sv1 = g_bucket[(size_t)d * CAP + 32 + lane];

    float4 ac = {0,0,0,0};
    float sum = 0.0f;
    int iters = (deg + 7) >> 3;
    for (int it = 0; it < iters; it++) {
        int e = slot + it * 8;
        int i0 = __shfl_sync(FULL, sv0, e & 31);
        int i1 = __shfl_sync(FULL, sv1, e & 31);
        bool act = (e < deg);
        int s = act ? ((e < 32) ? i0 : i1) : 0;
        float4 kv = ((const float4*)(g_k2 + (size_t)s * D2))[sub];
        float p = qv.x*kv.x + qv.y*kv.y + qv.z*kv.z + qv.w*kv.w;
        p += __shfl_xor_sync(FULL, p, 1, 4);
        p += __shfl_xor_sync(FULL, p, 2, 4);
        float w = act ? __expf(fminf(p * scale, 75.0f)) : 0.0f;
        float4 vv = ((const float4*)(g_v2 + (size_t)s * D2))[sub];
        ac.x = fmaf(vv.x, w, ac.x); ac.y = fmaf(vv.y, w, ac.y);
        ac.z = fmaf(vv.z, w, ac.z); ac.w = fmaf(vv.w, w, ac.w);
        sum += w;
    }
    #pragma unroll
    for (int o = 4; o < 32; o <<= 1) {
        ac.x += __shfl_xor_sync(FULL, ac.x, o); ac.y += __shfl_xor_sync(FULL, ac.y, o);
        ac.z += __shfl_xor_sync(FULL, ac.z, o); ac.w += __shfl_xor_sync(FULL, ac.w, o);
        sum  += __shfl_xor_sync(FULL, sum,  o);
    }
    float4 sk = ((const float4*)(g_sk2 + (size_t)d * D2))[sub];
    float inv = 1.0f / (sum + 1e-16f);
    float v0 = fmaxf(ac.x*inv + sk.x, 0.0f);
    float v1 = fmaxf(ac.y*inv + sk.y, 0.0f);
    float v2 = fmaxf(ac.z*inv + sk.z, 0.0f);
    float v3 = fmaxf(ac.w*inv + sk.w, 0.0f);
    int i0 = sub * 4;
    float p0 = v0*__ldg(Wo+i0*2)   + v1*__ldg(Wo+(i0+1)*2)   + v2*__ldg(Wo+(i0+2)*2)   + v3*__ldg(Wo+(i0+3)*2);
    float p1 = v0*__ldg(Wo+i0*2+1) + v1*__ldg(Wo+(i0+1)*2+1) + v2*__ldg(Wo+(i0+2)*2+1) + v3*__ldg(Wo+(i0+3)*2+1);
    p0 += __shfl_xor_sync(FULL, p0, 1, 4);
    p0 += __shfl_xor_sync(FULL, p0, 2, 4);
    p1 += __shfl_xor_sync(FULL, p1, 1, 4);
    p1 += __shfl_xor_sync(FULL, p1, 2, 4);
    if (lane == 0) {
        out[d * 2 + 0] = p0 + __ldg(bo);
        out[d * 2 + 1] = p1 + __ldg(bo + 1);
    }
}

// ---------------- launch ------------------------------------------------------
extern "C" void kernel_launch(void* const* d_in, const int* in_sizes, int n_in,
                              void* d_out, int out_size) {
    const int*   ei  = (const int*)d_in[0];
    const float* emb = (const float*)d_in[1];
    const float *Wq1 = (const float*)d_in[2],  *bq1 = (const float*)d_in[3];
    const float *Wk1 = (const float*)d_in[4],  *bk1 = (const float*)d_in[5];
    const float *Wv1 = (const float*)d_in[6],  *bv1 = (const float*)d_in[7];
    const float *Ws1 = (const float*)d_in[8],  *bs1 = (const float*)d_in[9];
    const float *Wq2 = (const float*)d_in[10], *bq2 = (const float*)d_in[11];
    const float *Wk2 = (const float*)d_in[12], *bk2 = (const float*)d_in[13];
    const float *Wv2 = (const float*)d_in[14], *bv2 = (const float*)d_in[15];
    const float *Ws2 = (const float*)d_in[16], *bs2 = (const float*)d_in[17];
    const float *Wo  = (const float*)d_in[18], *bo  = (const float*)d_in[19];
    float* out = (float*)d_out;

    int E = in_sizes[0] / 2;
    int N = in_sizes[1] / D1;
    const int* src = ei;
    const int* dst = ei + E;

    const int TB = 256;
    int gP1 = (N + 7) / 8;
    int gSC = (E + TB - 1) / TB;
    int gW  = (N + 7) / 8;                     // 8 warps = 8 dsts / block

    float s1 = 1.0f / sqrtf((float)D1);
    float s2 = 1.0f / sqrtf((float)D2);

    proj1_kernel<<<gP1, TB>>>(emb, Wq1, bq1, Wk1, bk1, Wv1, bv1, Ws1, bs1, N);
    scatter_kernel<<<gSC, TB>>>(src, dst, E);
    edgeL1_proj2_kernel<<<gW, TB>>>(Wq2, bq2, Wk2, bk2, Wv2, bv2, Ws2, bs2, s1, N);
    edgeL2_out_kernel<<<gW, TB>>>(Wo, bo, out, s2, N);
}

// round 9
// speedup vs baseline: 1.6193x; 1.0960x over previous
#include <cuda_runtime.h>
#include <math_constants.h>

#define N_NODES 100000
#define N_EDGES 1600000
#define D1 32
#define D2 16

// ---------------- scratch (device globals; no allocation allowed) -------------
__device__ __align__(16) float g_q   [N_NODES * D1];
__device__ __align__(16) float g_k   [N_NODES * D1];
__device__ __align__(16) float g_v   [N_NODES * D1];
__device__ __align__(16) float g_skip[N_NODES * D1];
__device__ __align__(16) float g_acc [N_NODES * D1];
__device__ __align__(16) float g_q2  [N_NODES * D2];
__device__ __align__(16) float g_kv2 [N_NODES * 2 * D2];  // k | v interleaved, 128B rows
__device__ __align__(16) float g_sk2 [N_NODES * D2];
__device__ float g_sum [N_NODES];

#define FULL 0xffffffffu

// ---------------- helpers ----------------------------------------------------
__device__ __forceinline__ void redAdd4(float4* p, float a, float b, float c, float d) {
    asm volatile("red.global.add.v4.f32 [%0], {%1,%2,%3,%4};"
                 :: "l"(p), "f"(a), "f"(b), "f"(c), "f"(d) : "memory");
}

// ---------------- layer-1 projection, fused with acc/sum zeroing -------------
__global__ __launch_bounds__(256) void proj1_kernel(
        const float* __restrict__ x,
        const float* __restrict__ Wq, const float* __restrict__ bq,
        const float* __restrict__ Wk, const float* __restrict__ bk,
        const float* __restrict__ Wv, const float* __restrict__ bv,
        const float* __restrict__ Ws, const float* __restrict__ bs,
        int n) {
    constexpr int NPB = 256 / D1;              // 8 nodes per block
    __shared__ float sW[4][D1 * D1];
    __shared__ float sx[NPB][D1];
    int t = threadIdx.x;
    for (int i = t; i < D1 * D1; i += 256) {
        sW[0][i] = Wq[i]; sW[1][i] = Wk[i]; sW[2][i] = Wv[i]; sW[3][i] = Ws[i];
    }
    int node0 = blockIdx.x * NPB;
    for (int i = t; i < NPB * D1; i += 256) {
        int nn = node0 + (i >> 5);
        sx[i >> 5][i & 31] = (nn < n) ? x[(size_t)nn * D1 + (i & 31)] : 0.0f;
    }
    __syncthreads();
    int ln = t >> 5;
    int j  = t & 31;
    int node = node0 + ln;
    if (node >= n) return;
    float aq = bq[j], ak = bk[j], av = bv[j], as_ = bs[j];
    #pragma unroll
    for (int i = 0; i < D1; i++) {
        float xi = sx[ln][i];
        aq  = fmaf(xi, sW[0][i * D1 + j], aq);
        ak  = fmaf(xi, sW[1][i * D1 + j], ak);
        av  = fmaf(xi, sW[2][i * D1 + j], av);
        as_ = fmaf(xi, sW[3][i * D1 + j], as_);
    }
    int o = node * D1 + j;
    g_q[o] = aq; g_k[o] = ak; g_v[o] = av; g_skip[o] = as_;
    g_acc[o] = 0.0f;
    if (j == 0) g_sum[node] = 0.0f;
}

// ---------------- layer-1 edge pass: 8 lanes per edge -------------------------
// One LDG.128 per array per edge (full 128B row in one wavefront); one RED.v4.
__global__ __launch_bounds__(256) void edge1_kernel(
        const int* __restrict__ src, const int* __restrict__ dst,
        float scale, int nE) {
    int tid = blockIdx.x * blockDim.x + threadIdx.x;
    int e = tid >> 3, sub = tid & 7;
    if (e >= nE) return;
    int s = src[e], d = dst[e];
    float4 q = ((const float4*)(g_q + (size_t)d * D1))[sub];
    float4 k = ((const float4*)(g_k + (size_t)s * D1))[sub];
    float p = q.x*k.x + q.y*k.y + q.z*k.z + q.w*k.w;
    p += __shfl_xor_sync(FULL, p, 1, 8);
    p += __shfl_xor_sync(FULL, p, 2, 8);
    p += __shfl_xor_sync(FULL, p, 4, 8);
    float w = __expf(fminf(p * scale, 75.0f));   // overflow guard only
    if (sub == 0) atomicAdd(g_sum + d, w);
    float4 v = ((const float4*)(g_v + (size_t)s * D1))[sub];
    redAdd4(((float4*)(g_acc + (size_t)d * D1)) + sub, v.x*w, v.y*w, v.z*w, v.w*w);
}

// ---------------- fused: finalize layer 1 -> SMEM h -> layer-2 projection ----
__global__ __launch_bounds__(256) void fin1_proj2_kernel(
        const float* __restrict__ Wq, const float* __restrict__ bq,
        const float* __restrict__ Wk, const float* __restrict__ bk,
        const float* __restrict__ Wv, const float* __restrict__ bv,
        const float* __restrict__ Ws, const float* __restrict__ bs,
        int n) {
    constexpr int NPB = 256 / D2;              // 16 nodes per block
    __shared__ float sW[4][D1 * D2];
    __shared__ float sh[NPB][D1];
    int t = threadIdx.x;
    for (int i = t; i < D1 * D2; i += 256) {
        sW[0][i] = Wq[i]; sW[1][i] = Wk[i]; sW[2][i] = Wv[i]; sW[3][i] = Ws[i];
    }
    int node0 = blockIdx.x * NPB;
    #pragma unroll
    for (int r = 0; r < 2; r++) {
        int i = t + r * 256;                   // 0..511 = 16 nodes * 32 dims
        int ln = i >> 5;
        int node = node0 + ln;
        if (node < n) {
            int o = node * D1 + (i & 31);
            float val = g_acc[o] / (g_sum[node] + 1e-16f) + g_skip[o];
            sh[ln][i & 31] = fmaxf(val, 0.0f);
            g_acc[o] = 0.0f;                   // re-init for layer-2 edge pass
            if ((i & 31) == 0) g_sum[node] = 0.0f;
        }
    }
    __syncthreads();
    // Phase B: projection 32 -> 16. thread = (node ln, j); computes all 4 outputs.
    int ln = t >> 4;
    int j  = t & 15;
    int node = node0 + ln;
    if (node >= n) return;
    float aq = bq[j], ak = bk[j], av = bv[j], as_ = bs[j];
    #pragma unroll
    for (int i = 0; i < D1; i++) {
        float hi = sh[ln][i];
        aq  = fmaf(hi, sW[0][i * D2 + j], aq);
        ak  = fmaf(hi, sW[1][i * D2 + j], ak);
        av  = fmaf(hi, sW[2][i * D2 + j], av);
        as_ = fmaf(hi, sW[3][i * D2 + j], as_);
    }
    g_q2 [node * D2 + j] = aq;
    g_kv2[node * 2 * D2 + j]      = ak;        // k half of kv row
    g_kv2[node * 2 * D2 + D2 + j] = av;        // v half of kv row
    g_sk2[node * D2 + j] = as_;
}

// ---------------- layer-2 edge pass: 8 lanes per edge, kv interleaved ---------
// lanes 0-3: k chunk (dot); lanes 4-7: v chunk (RED). One kv LDG per edge.
__global__ __launch_bounds__(256) void edge2_kernel(
        const int* __restrict__ src, const int* __restrict__ dst,
        float scale, int nE) {
    int tid = blockIdx.x * blockDim.x + threadIdx.x;
    int e = tid >> 3, sub = tid & 7;
    if (e >= nE) return;
    int s = src[e], d = dst[e];
    float4 kv = ((const float4*)(g_kv2 + (size_t)s * 2 * D2))[sub];
    float p = 0.0f;
    if (sub < 4) {
        float4 q = ((const float4*)(g_q2 + (size_t)d * D2))[sub];
        p = q.x*kv.x + q.y*kv.y + q.z*kv.z + q.w*kv.w;
    }
    p += __shfl_xor_sync(FULL, p, 1, 8);
    p += __shfl_xor_sync(FULL, p, 2, 8);
    p += __shfl_xor_sync(FULL, p, 4, 8);
    float w = __expf(fminf(p * scale, 75.0f));
    if (sub == 0) atomicAdd(g_sum + d, w);
    if (sub >= 4)
        redAdd4(((float4*)(g_acc + (size_t)d * D2)) + (sub - 4),
                kv.x*w, kv.y*w, kv.z*w, kv.w*w);
}

// ---------------- finalize layer 2 + output linear (16 -> 2), fused ----------
__global__ __launch_bounds__(256) void finalize2_out_kernel(
        const float* __restrict__ Wo, const float* __restrict__ bo,
        float* __restrict__ out, int n) {
    int tid = blockIdx.x * blockDim.x + threadIdx.x;
    if (tid >= n * D2) return;
    int node = tid >> 4;
    int i = tid & 15;
    float val = g_acc[tid] / (g_sum[node] + 1e-16f) + g_sk2[tid];
    val = fmaxf(val, 0.0f);
    float p0 = val * Wo[i * 2 + 0];
    float p1 = val * Wo[i * 2 + 1];
    unsigned m = __activemask();
    #pragma unroll
    for (int o = 8; o; o >>= 1) {
        p0 += __shfl_xor_sync(m, p0, o, 16);
        p1 += __shfl_xor_sync(m, p1, o, 16);
    }
    if (i == 0) {
        out[node * 2 + 0] = p0 + bo[0];
        out[node * 2 + 1] = p1 + bo[1];
    }
}

// ---------------- launch ------------------------------------------------------
extern "C" void kernel_launch(void* const* d_in, const int* in_sizes, int n_in,
                              void* d_out, int out_size) {
    const int*   ei  = (const int*)d_in[0];
    const float* emb = (const float*)d_in[1];
    const float *Wq1 = (const float*)d_in[2],  *bq1 = (const float*)d_in[3];
    const float *Wk1 = (const float*)d_in[4],  *bk1 = (const float*)d_in[5];
    const float *Wv1 = (const float*)d_in[6],  *bv1 = (const float*)d_in[7];
    const float *Ws1 = (const float*)d_in[8],  *bs1 = (const float*)d_in[9];
    const float *Wq2 = (const float*)d_in[10], *bq2 = (const float*)d_in[11];
    const float *Wk2 = (const float*)d_in[12], *bk2 = (const float*)d_in[13];
    const float *Wv2 = (const float*)d_in[14], *bv2 = (const float*)d_in[15];
    const float *Ws2 = (const float*)d_in[16], *bs2 = (const float*)d_in[17];
    const float *Wo  = (const float*)d_in[18], *bo  = (const float*)d_in[19];
    float* out = (float*)d_out;

    int E = in_sizes[0] / 2;
    int N = in_sizes[1] / D1;
    const int* src = ei;
    const int* dst = ei + E;

    const int TB = 256;
    int gP1 = (N + 7) / 8;                     // 8 nodes / block
    int gE8 = (int)(((size_t)E * 8 + TB - 1) / TB);  // 8 lanes / edge
    int gFP = (N + 15) / 16;                   // 16 nodes / block
    int gN2 = (N * D2 + TB - 1) / TB;

    float s1 = 1.0f / sqrtf((float)D1);
    float s2 = 1.0f / sqrtf((float)D2);

    // ---- layer 1 (d=32) ----
    proj1_kernel<<<gP1, TB>>>(emb, Wq1, bq1, Wk1, bk1, Wv1, bv1, Ws1, bs1, N);
    edge1_kernel<<<gE8, TB>>>(src, dst, s1, E);

    // ---- finalize 1 + projection 2 (fused) ----
    fin1_proj2_kernel<<<gFP, TB>>>(Wq2, bq2, Wk2, bk2, Wv2, bv2, Ws2, bs2, N);

    // ---- layer 2 (d=16) ----
    edge2_kernel<<<gE8, TB>>>(src, dst, s2, E);
    finalize2_out_kernel<<<gN2, TB>>>(Wo, bo, out, N);
}